// round 1
// baseline (speedup 1.0000x reference)
#include <cuda_runtime.h>
#include <math.h>

#define NTOK 8192
#define DDIM 1024
#define NEXP 8
#define FDIM 3264

#define BM 128
#define BN 64
#define BK 16

// ---- device scratch (module-static; no runtime allocation) ----
__device__ int   g_counts[NEXP];
__device__ int   g_tokens[NEXP * NTOK];
__device__ float g_wts[NEXP * NTOK];
__device__ float g_H[(size_t)NEXP * NTOK * FDIM];   // compacted expert activations

// ============================================================
// init: zero output accumulator + per-expert counters
// ============================================================
__global__ void init_kernel(float* __restrict__ out, int n) {
    int i = blockIdx.x * blockDim.x + threadIdx.x;
    if (i < NEXP) g_counts[i] = 0;
    if (i < n) out[i] = 0.f;
}

// ============================================================
// router: softmax over 8 experts, top-2, normalized weights,
// compact per-expert (token, weight) lists. One warp per token.
// ============================================================
__global__ void router_kernel(const float* __restrict__ x,
                              const float* __restrict__ gw,
                              const float* __restrict__ gb) {
    int warp = (blockIdx.x * blockDim.x + threadIdx.x) >> 5;
    int lane = threadIdx.x & 31;
    if (warp >= NTOK) return;
    const float* xr = x + (size_t)warp * DDIM;

    float acc[NEXP];
#pragma unroll
    for (int e = 0; e < NEXP; e++) acc[e] = 0.f;

    for (int k = lane; k < DDIM; k += 32) {
        float xv = xr[k];
#pragma unroll
        for (int e = 0; e < NEXP; e++) acc[e] += xv * gw[e * DDIM + k];
    }
#pragma unroll
    for (int e = 0; e < NEXP; e++) {
#pragma unroll
        for (int off = 16; off; off >>= 1)
            acc[e] += __shfl_xor_sync(0xffffffffu, acc[e], off);
    }
    if (lane == 0) {
        float mx = -1e30f;
#pragma unroll
        for (int e = 0; e < NEXP; e++) { acc[e] += gb[e]; mx = fmaxf(mx, acc[e]); }
        float p[NEXP];
#pragma unroll
        for (int e = 0; e < NEXP; e++) p[e] = expf(acc[e] - mx);

        // top-2 (first index wins on ties, matching lax.top_k)
        int i1 = 0; float v1 = p[0];
#pragma unroll
        for (int e = 1; e < NEXP; e++) if (p[e] > v1) { v1 = p[e]; i1 = e; }
        int i2 = -1; float v2 = -1.f;
#pragma unroll
        for (int e = 0; e < NEXP; e++)
            if (e != i1 && p[e] > v2) { v2 = p[e]; i2 = e; }

        float inv = 1.f / (v1 + v2);    // softmax denom cancels in the ratio
        float w1 = v1 * inv, w2 = v2 * inv;

        int s1 = atomicAdd(&g_counts[i1], 1);
        g_tokens[i1 * NTOK + s1] = warp;
        g_wts[i1 * NTOK + s1]    = w1;
        int s2 = atomicAdd(&g_counts[i2], 1);
        g_tokens[i2 * NTOK + s2] = warp;
        g_wts[i2 * NTOK + s2]    = w2;
    }
}

// ============================================================
// GEMM 1 (gather): per expert e, rows = compacted tokens
//   G = Xe @ gp_w[e]^T + gp_b[e];  U = Xe @ up_w[e]^T + up_b[e]
//   H = silu(G * U)   -> g_H
// Tile 128x64x16, 256 threads, 8x4 register tile, dual accumulators.
// ============================================================
__global__ __launch_bounds__(256) void gemm_gu_kernel(
    const float* __restrict__ x,
    const float* __restrict__ gpw, const float* __restrict__ gpb,
    const float* __restrict__ upw, const float* __restrict__ upb) {

    int e   = blockIdx.z;
    int cnt = g_counts[e];
    int m0  = blockIdx.x * BM;
    if (m0 >= cnt) return;
    int n0  = blockIdx.y * BN;

    __shared__ __align__(16) float As[BK][132];
    __shared__ __align__(16) float Bgs[BK][68];
    __shared__ __align__(16) float Bus[BK][68];

    int tid  = threadIdx.x;
    int kq   = tid & 3;          // which float4 of the 16-wide k strip
    int arow = tid >> 2;         // 0..63 (rows arow and arow+64)
    int bn   = tid >> 2;         // 0..63

    int tok0 = (m0 + arow      < cnt) ? g_tokens[e * NTOK + m0 + arow]      : -1;
    int tok1 = (m0 + arow + 64 < cnt) ? g_tokens[e * NTOK + m0 + arow + 64] : -1;

    const float* gpwp = gpw + ((size_t)e * FDIM + n0 + bn) * DDIM + kq * 4;
    const float* upwp = upw + ((size_t)e * FDIM + n0 + bn) * DDIM + kq * 4;

    int tm0 = (tid >> 4) * 8;
    int tn0 = (tid & 15) * 4;

    float cg[8][4], cu[8][4];
#pragma unroll
    for (int i = 0; i < 8; i++)
#pragma unroll
        for (int j = 0; j < 4; j++) { cg[i][j] = 0.f; cu[i][j] = 0.f; }

    float4 av0, av1, bgv, buv;
    av0 = (tok0 >= 0) ? *(const float4*)(x + (size_t)tok0 * DDIM + kq * 4)
                      : make_float4(0.f, 0.f, 0.f, 0.f);
    av1 = (tok1 >= 0) ? *(const float4*)(x + (size_t)tok1 * DDIM + kq * 4)
                      : make_float4(0.f, 0.f, 0.f, 0.f);
    bgv = *(const float4*)(gpwp);
    buv = *(const float4*)(upwp);

    for (int k0 = 0; k0 < DDIM; k0 += BK) {
        __syncthreads();
        int kb = kq * 4;
        As[kb + 0][arow] = av0.x; As[kb + 1][arow] = av0.y;
        As[kb + 2][arow] = av0.z; As[kb + 3][arow] = av0.w;
        As[kb + 0][arow + 64] = av1.x; As[kb + 1][arow + 64] = av1.y;
        As[kb + 2][arow + 64] = av1.z; As[kb + 3][arow + 64] = av1.w;
        Bgs[kb + 0][bn] = bgv.x; Bgs[kb + 1][bn] = bgv.y;
        Bgs[kb + 2][bn] = bgv.z; Bgs[kb + 3][bn] = bgv.w;
        Bus[kb + 0][bn] = buv.x; Bus[kb + 1][bn] = buv.y;
        Bus[kb + 2][bn] = buv.z; Bus[kb + 3][bn] = buv.w;
        __syncthreads();

        int k1 = k0 + BK;
        if (k1 < DDIM) {   // prefetch next strip before the FMA wall
            av0 = (tok0 >= 0) ? *(const float4*)(x + (size_t)tok0 * DDIM + k1 + kq * 4)
                              : make_float4(0.f, 0.f, 0.f, 0.f);
            av1 = (tok1 >= 0) ? *(const float4*)(x + (size_t)tok1 * DDIM + k1 + kq * 4)
                              : make_float4(0.f, 0.f, 0.f, 0.f);
            bgv = *(const float4*)(gpwp + k1);
            buv = *(const float4*)(upwp + k1);
        }

#pragma unroll
        for (int kk = 0; kk < BK; kk++) {
            float4 a0 = *(const float4*)&As[kk][tm0];
            float4 a1 = *(const float4*)&As[kk][tm0 + 4];
            float4 bg = *(const float4*)&Bgs[kk][tn0];
            float4 bu = *(const float4*)&Bus[kk][tn0];
            float a[8] = {a0.x, a0.y, a0.z, a0.w, a1.x, a1.y, a1.z, a1.w};
            float bgA[4] = {bg.x, bg.y, bg.z, bg.w};
            float buA[4] = {bu.x, bu.y, bu.z, bu.w};
#pragma unroll
            for (int i = 0; i < 8; i++)
#pragma unroll
                for (int j = 0; j < 4; j++) {
                    cg[i][j] += a[i] * bgA[j];
                    cu[i][j] += a[i] * buA[j];
                }
        }
    }

    float gbv[4], ubv[4];
#pragma unroll
    for (int j = 0; j < 4; j++) {
        gbv[j] = gpb[e * FDIM + n0 + tn0 + j];
        ubv[j] = upb[e * FDIM + n0 + tn0 + j];
    }
#pragma unroll
    for (int i = 0; i < 8; i++) {
        int slot = m0 + tm0 + i;
        if (slot >= cnt) continue;
        float hh[4];
#pragma unroll
        for (int j = 0; j < 4; j++) {
            float g = cg[i][j] + gbv[j];
            float u = cu[i][j] + ubv[j];
            float z = g * u;
            hh[j] = z / (1.f + expf(-z));   // silu
        }
        *(float4*)(g_H + ((size_t)(e * NTOK) + slot) * FDIM + n0 + tn0) =
            make_float4(hh[0], hh[1], hh[2], hh[3]);
    }
}

// ============================================================
// GEMM 2: Y = H @ down_w[e]^T (+ down_b), scaled by gate weight,
// atomicAdd scatter into out. Tile 128x64x16 over K=FDIM.
// ============================================================
__global__ __launch_bounds__(256) void gemm_down_kernel(
    const float* __restrict__ dww, const float* __restrict__ dwb,
    float* __restrict__ out) {

    int e   = blockIdx.z;
    int cnt = g_counts[e];
    int m0  = blockIdx.x * BM;
    if (m0 >= cnt) return;
    int n0  = blockIdx.y * BN;   // over DDIM

    __shared__ __align__(16) float As[BK][132];
    __shared__ __align__(16) float Bs[BK][68];

    int tid  = threadIdx.x;
    int kq   = tid & 3;
    int arow = tid >> 2;
    int bn   = tid >> 2;

    const float* ap0 = g_H + ((size_t)(e * NTOK) + m0 + arow) * FDIM + kq * 4;
    const float* ap1 = ap0 + (size_t)64 * FDIM;
    const float* bp  = dww + ((size_t)e * DDIM + n0 + bn) * FDIM + kq * 4;

    int tm0 = (tid >> 4) * 8;
    int tn0 = (tid & 15) * 4;

    float c[8][4];
#pragma unroll
    for (int i = 0; i < 8; i++)
#pragma unroll
        for (int j = 0; j < 4; j++) c[i][j] = 0.f;

    float4 av0 = *(const float4*)(ap0);
    float4 av1 = *(const float4*)(ap1);
    float4 bv  = *(const float4*)(bp);

    for (int k0 = 0; k0 < FDIM; k0 += BK) {
        __syncthreads();
        int kb = kq * 4;
        As[kb + 0][arow] = av0.x; As[kb + 1][arow] = av0.y;
        As[kb + 2][arow] = av0.z; As[kb + 3][arow] = av0.w;
        As[kb + 0][arow + 64] = av1.x; As[kb + 1][arow + 64] = av1.y;
        As[kb + 2][arow + 64] = av1.z; As[kb + 3][arow + 64] = av1.w;
        Bs[kb + 0][bn] = bv.x; Bs[kb + 1][bn] = bv.y;
        Bs[kb + 2][bn] = bv.z; Bs[kb + 3][bn] = bv.w;
        __syncthreads();

        int k1 = k0 + BK;
        if (k1 < FDIM) {
            av0 = *(const float4*)(ap0 + k1);
            av1 = *(const float4*)(ap1 + k1);
            bv  = *(const float4*)(bp + k1);
        }

#pragma unroll
        for (int kk = 0; kk < BK; kk++) {
            float4 a0 = *(const float4*)&As[kk][tm0];
            float4 a1 = *(const float4*)&As[kk][tm0 + 4];
            float4 b  = *(const float4*)&Bs[kk][tn0];
            float a[8] = {a0.x, a0.y, a0.z, a0.w, a1.x, a1.y, a1.z, a1.w};
            float bA[4] = {b.x, b.y, b.z, b.w};
#pragma unroll
            for (int i = 0; i < 8; i++)
#pragma unroll
                for (int j = 0; j < 4; j++) c[i][j] += a[i] * bA[j];
        }
    }

    float dbv[4];
#pragma unroll
    for (int j = 0; j < 4; j++) dbv[j] = dwb[e * DDIM + n0 + tn0 + j];

#pragma unroll
    for (int i = 0; i < 8; i++) {
        int slot = m0 + tm0 + i;
        if (slot >= cnt) continue;
        int   tok = g_tokens[e * NTOK + slot];
        float w   = g_wts[e * NTOK + slot];
        float* op = out + (size_t)tok * DDIM + n0 + tn0;
#pragma unroll
        for (int j = 0; j < 4; j++)
            atomicAdd(op + j, (c[i][j] + dbv[j]) * w);
    }
}

// ============================================================
extern "C" void kernel_launch(void* const* d_in, const int* in_sizes, int n_in,
                              void* d_out, int out_size) {
    const float* x      = (const float*)d_in[0];
    const float* gate_w = (const float*)d_in[1];
    const float* gate_b = (const float*)d_in[2];
    const float* up_w   = (const float*)d_in[3];
    const float* up_b   = (const float*)d_in[4];
    const float* gp_w   = (const float*)d_in[5];
    const float* gp_b   = (const float*)d_in[6];
    const float* down_w = (const float*)d_in[7];
    const float* down_b = (const float*)d_in[8];
    float* out = (float*)d_out;

    (void)in_sizes; (void)n_in;

    init_kernel<<<(out_size + 255) / 256, 256>>>(out, out_size);
    router_kernel<<<NTOK / 8, 256>>>(x, gate_w, gate_b);

    dim3 gA(NTOK / BM, FDIM / BN, NEXP);
    gemm_gu_kernel<<<gA, 256>>>(x, gp_w, gp_b, up_w, up_b);

    dim3 gB(NTOK / BM, DDIM / BN, NEXP);
    gemm_down_kernel<<<gB, 256>>>(down_w, down_b, out);
}

// round 4
// speedup vs baseline: 4.5443x; 4.5443x over previous
#include <cuda_runtime.h>
#include <math.h>
#include <stdint.h>

#define NTOK 8192
#define DDIM 1024
#define NEXP 8
#define FDIM 3264
#define NROW (NEXP * NTOK)

#define BM 128
#define BN 128
#define BK 32
#define STAGES 4
#define SSTR 36                       // smem row stride in floats (conflict-free)
#define TILE_F (128 * SSTR)           // floats per 128-row tile
#define TILE_B (TILE_F * 4)           // 18432 bytes

// ---------------- device scratch ----------------
__device__ int   g_counts[NEXP];
__device__ int   g_pos[NTOK * 2];
__device__ int   g_tok[NROW];
__device__ float g_wts[NROW];
__device__ float g_Xe[(size_t)NROW * DDIM];
__device__ float g_H [(size_t)NROW * FDIM];

// ---------------- helpers ----------------
__device__ __forceinline__ uint32_t smem_u32(const void* p) {
    uint32_t a;
    asm("{ .reg .u64 t; cvta.to.shared.u64 t, %1; cvt.u32.u64 %0, t; }" : "=r"(a) : "l"(p));
    return a;
}
__device__ __forceinline__ uint32_t f2tf(float x) {      // round-to-nearest tf32
    uint32_t u;
    asm("cvt.rna.tf32.f32 %0, %1;" : "=r"(u) : "f"(x));
    return u;
}
__device__ __forceinline__ void cp16(uint32_t dst, const void* src, bool valid) {
    uint32_t sz = valid ? 16u : 0u;
    asm volatile("cp.async.cg.shared.global [%0], [%1], 16, %2;"
                 :: "r"(dst), "l"(src), "r"(sz));
}
__device__ __forceinline__ void cp_commit() {
    asm volatile("cp.async.commit_group;" ::: "memory");
}
__device__ __forceinline__ void cp_wait2() {
    asm volatile("cp.async.wait_group 2;" ::: "memory");
}
__device__ __forceinline__ void mma8(float* c, const uint32_t* a, const uint32_t* b) {
    asm("mma.sync.aligned.m16n8k8.row.col.f32.tf32.tf32.f32 "
        "{%0,%1,%2,%3}, {%4,%5,%6,%7}, {%8,%9}, {%0,%1,%2,%3};"
        : "+f"(c[0]), "+f"(c[1]), "+f"(c[2]), "+f"(c[3])
        : "r"(a[0]), "r"(a[1]), "r"(a[2]), "r"(a[3]), "r"(b[0]), "r"(b[1]));
}

// ============================================================
// init / router / gather
// ============================================================
__global__ void init_kernel(float* __restrict__ out, int n) {
    int i = blockIdx.x * blockDim.x + threadIdx.x;
    if (i < NEXP) g_counts[i] = 0;
    if (i < n) out[i] = 0.f;
}

__global__ void router_kernel(const float* __restrict__ x,
                              const float* __restrict__ gw,
                              const float* __restrict__ gb) {
    int warp = (blockIdx.x * blockDim.x + threadIdx.x) >> 5;
    int lane = threadIdx.x & 31;
    if (warp >= NTOK) return;
    const float* xr = x + (size_t)warp * DDIM;

    float acc[NEXP];
#pragma unroll
    for (int e = 0; e < NEXP; e++) acc[e] = 0.f;
    for (int k = lane; k < DDIM; k += 32) {
        float xv = xr[k];
#pragma unroll
        for (int e = 0; e < NEXP; e++) acc[e] += xv * gw[e * DDIM + k];
    }
#pragma unroll
    for (int e = 0; e < NEXP; e++)
#pragma unroll
        for (int off = 16; off; off >>= 1)
            acc[e] += __shfl_xor_sync(0xffffffffu, acc[e], off);

    if (lane == 0) {
        float mx = -1e30f;
#pragma unroll
        for (int e = 0; e < NEXP; e++) { acc[e] += gb[e]; mx = fmaxf(mx, acc[e]); }
        float p[NEXP];
#pragma unroll
        for (int e = 0; e < NEXP; e++) p[e] = expf(acc[e] - mx);
        int i1 = 0; float v1 = p[0];
#pragma unroll
        for (int e = 1; e < NEXP; e++) if (p[e] > v1) { v1 = p[e]; i1 = e; }
        int i2 = -1; float v2 = -1.f;
#pragma unroll
        for (int e = 0; e < NEXP; e++) if (e != i1 && p[e] > v2) { v2 = p[e]; i2 = e; }
        float inv = 1.f / (v1 + v2);
        int s1 = atomicAdd(&g_counts[i1], 1);
        int s2 = atomicAdd(&g_counts[i2], 1);
        g_wts[i1 * NTOK + s1] = v1 * inv;
        g_wts[i2 * NTOK + s2] = v2 * inv;
        g_tok[i1 * NTOK + s1] = warp;
        g_tok[i2 * NTOK + s2] = warp;
        g_pos[2 * warp]     = i1 * NTOK + s1;
        g_pos[2 * warp + 1] = i2 * NTOK + s2;
    }
}

// gather x rows into per-expert slots, pre-rounded to tf32 (RNA)
__global__ __launch_bounds__(256) void gather_kernel(const float* __restrict__ x) {
    int t  = blockIdx.x;
    int p0 = g_pos[2 * t], p1 = g_pos[2 * t + 1];
    float4 v = ((const float4*)(x + (size_t)t * DDIM))[threadIdx.x];
    v.x = __uint_as_float(f2tf(v.x));
    v.y = __uint_as_float(f2tf(v.y));
    v.z = __uint_as_float(f2tf(v.z));
    v.w = __uint_as_float(f2tf(v.w));
    ((float4*)(g_Xe + (size_t)p0 * DDIM))[threadIdx.x] = v;
    ((float4*)(g_Xe + (size_t)p1 * DDIM))[threadIdx.x] = v;
}

// ============================================================
// GEMM1: [128 slot] x [128 f] tile, K=1024 over Xe, computes G and U,
// silu epilogue -> g_H (tf32-rounded)
// ============================================================
__global__ __launch_bounds__(256, 1) void gemm1_kernel(
    const float* __restrict__ gpw, const float* __restrict__ gpb,
    const float* __restrict__ upw, const float* __restrict__ upb) {

    int e   = blockIdx.z;
    int cnt = g_counts[e];
    int m0  = blockIdx.y * BM;
    if (m0 >= cnt) return;
    int n0  = blockIdx.x * BN;
    int ebase = e * NTOK;

    extern __shared__ __align__(16) float sm[];
    uint32_t sbase = smem_u32(sm);

    int tid = threadIdx.x;
    int wid = tid >> 5, lane = tid & 31;
    int wr = wid >> 2, wc = wid & 3;          // 2 x 4 warp grid
    int g = lane >> 2, t = lane & 3;

    const float* srcA = g_Xe + (size_t)(ebase + m0) * DDIM;

    float cg[4][4][4], cu[4][4][4];
#pragma unroll
    for (int i = 0; i < 4; i++)
#pragma unroll
        for (int j = 0; j < 4; j++)
#pragma unroll
            for (int r = 0; r < 4; r++) { cg[i][j][r] = 0.f; cu[i][j][r] = 0.f; }

    const int KT = DDIM / BK;                 // 32

    // ---- per-stage load: 12 cp.asyncs per thread ----
    auto issue = [&](int kt, int st) {
        int k0 = kt * BK;
        uint32_t sA = sbase + st * (3 * TILE_B);
        uint32_t sG = sA + TILE_B;
        uint32_t sU = sG + TILE_B;
#pragma unroll
        for (int i = 0; i < 4; i++) {
            int c = i * 256 + tid;
            int row = c >> 3, kc = c & 7;
            cp16(sA + (row * SSTR + kc * 4) * 4,
                 srcA + (size_t)row * DDIM + k0 + kc * 4, true);
            int nrow = n0 + row;
            bool ok = nrow < FDIM;
            int nr = ok ? nrow : (FDIM - 1);
            cp16(sG + (row * SSTR + kc * 4) * 4,
                 gpw + ((size_t)e * FDIM + nr) * DDIM + k0 + kc * 4, ok);
            cp16(sU + (row * SSTR + kc * 4) * 4,
                 upw + ((size_t)e * FDIM + nr) * DDIM + k0 + kc * 4, ok);
        }
        cp_commit();
    };

#pragma unroll
    for (int s = 0; s < STAGES - 1; s++) issue(s, s);

    for (int kt = 0; kt < KT; kt++) {
        cp_wait2();
        __syncthreads();
        if (kt + STAGES - 1 < KT) issue(kt + STAGES - 1, (kt + STAGES - 1) % STAGES);
        else cp_commit();

        int st = kt % STAGES;
        const float* As = sm + st * (3 * TILE_F);
        const float* Gs = As + TILE_F;
        const float* Us = Gs + TILE_F;

#pragma unroll
        for (int kk = 0; kk < 4; kk++) {
            int kb = kk * 8;
            uint32_t a[4][4];
#pragma unroll
            for (int mt = 0; mt < 4; mt++) {
                int mr = wr * 64 + mt * 16 + g;
                a[mt][0] = __float_as_uint(As[mr * SSTR + kb + t]);
                a[mt][1] = __float_as_uint(As[(mr + 8) * SSTR + kb + t]);
                a[mt][2] = __float_as_uint(As[mr * SSTR + kb + t + 4]);
                a[mt][3] = __float_as_uint(As[(mr + 8) * SSTR + kb + t + 4]);
            }
            uint32_t bg[4][2], bu[4][2];
#pragma unroll
            for (int nt = 0; nt < 4; nt++) {
                int nr = wc * 32 + nt * 8 + g;
                bg[nt][0] = f2tf(Gs[nr * SSTR + kb + t]);
                bg[nt][1] = f2tf(Gs[nr * SSTR + kb + t + 4]);
                bu[nt][0] = f2tf(Us[nr * SSTR + kb + t]);
                bu[nt][1] = f2tf(Us[nr * SSTR + kb + t + 4]);
            }
#pragma unroll
            for (int mt = 0; mt < 4; mt++)
#pragma unroll
                for (int nt = 0; nt < 4; nt++) {
                    mma8(cg[mt][nt], a[mt], bg[nt]);
                    mma8(cu[mt][nt], a[mt], bu[nt]);
                }
        }
    }

    // ---- epilogue: silu(g*u) -> g_H ----
#pragma unroll
    for (int mt = 0; mt < 4; mt++) {
        int mrow = wr * 64 + mt * 16 + g;
#pragma unroll
        for (int p = 0; p < 2; p++) {
            int slot = m0 + mrow + p * 8;
            bool live = slot < cnt;
            size_t hbase = ((size_t)ebase + slot) * FDIM;
#pragma unroll
            for (int nt = 0; nt < 4; nt++) {
                int col = n0 + wc * 32 + nt * 8 + 2 * t;
                if (live && col < FDIM) {
                    float2 gb = *(const float2*)(gpb + (size_t)e * FDIM + col);
                    float2 ub = *(const float2*)(upb + (size_t)e * FDIM + col);
                    float g0 = cg[mt][nt][2 * p + 0] + gb.x;
                    float g1 = cg[mt][nt][2 * p + 1] + gb.y;
                    float u0 = cu[mt][nt][2 * p + 0] + ub.x;
                    float u1 = cu[mt][nt][2 * p + 1] + ub.y;
                    float z0 = g0 * u0, z1 = g1 * u1;
                    float h0 = z0 / (1.f + expf(-z0));
                    float h1 = z1 / (1.f + expf(-z1));
                    float2 stv;
                    stv.x = __uint_as_float(f2tf(h0));
                    stv.y = __uint_as_float(f2tf(h1));
                    *(float2*)(g_H + hbase + col) = stv;
                }
            }
        }
    }
}

// ============================================================
// GEMM2: [128 slot] x [128 d] tile, K=3264 over g_H, weighted
// scatter-add into out (2 contributions/elem -> deterministic)
// ============================================================
__global__ __launch_bounds__(256, 1) void gemm2_kernel(
    const float* __restrict__ dww, const float* __restrict__ dwb,
    float* __restrict__ out) {

    int e   = blockIdx.z;
    int cnt = g_counts[e];
    int m0  = blockIdx.y * BM;
    if (m0 >= cnt) return;
    int n0  = blockIdx.x * BN;
    int ebase = e * NTOK;

    extern __shared__ __align__(16) float sm[];
    uint32_t sbase = smem_u32(sm);

    int tid = threadIdx.x;
    int wid = tid >> 5, lane = tid & 31;
    int wr = wid >> 2, wc = wid & 3;
    int g = lane >> 2, t = lane & 3;

    const float* srcA = g_H + (size_t)(ebase + m0) * FDIM;

    float c[4][4][4];
#pragma unroll
    for (int i = 0; i < 4; i++)
#pragma unroll
        for (int j = 0; j < 4; j++)
#pragma unroll
            for (int r = 0; r < 4; r++) c[i][j][r] = 0.f;

    const int KT = FDIM / BK;                 // 102

    auto issue = [&](int kt, int st) {
        int k0 = kt * BK;
        uint32_t sA = sbase + st * (2 * TILE_B);
        uint32_t sB = sA + TILE_B;
#pragma unroll
        for (int i = 0; i < 4; i++) {
            int cc = i * 256 + tid;
            int row = cc >> 3, kc = cc & 7;
            cp16(sA + (row * SSTR + kc * 4) * 4,
                 srcA + (size_t)row * FDIM + k0 + kc * 4, true);
            cp16(sB + (row * SSTR + kc * 4) * 4,
                 dww + ((size_t)e * DDIM + n0 + row) * FDIM + k0 + kc * 4, true);
        }
        cp_commit();
    };

#pragma unroll
    for (int s = 0; s < STAGES - 1; s++) issue(s, s);

    for (int kt = 0; kt < KT; kt++) {
        cp_wait2();
        __syncthreads();
        if (kt + STAGES - 1 < KT) issue(kt + STAGES - 1, (kt + STAGES - 1) % STAGES);
        else cp_commit();

        int st = kt % STAGES;
        const float* As = sm + st * (2 * TILE_F);
        const float* Bs = As + TILE_F;

#pragma unroll
        for (int kk = 0; kk < 4; kk++) {
            int kb = kk * 8;
            uint32_t a[4][4];
#pragma unroll
            for (int mt = 0; mt < 4; mt++) {
                int mr = wr * 64 + mt * 16 + g;
                a[mt][0] = __float_as_uint(As[mr * SSTR + kb + t]);
                a[mt][1] = __float_as_uint(As[(mr + 8) * SSTR + kb + t]);
                a[mt][2] = __float_as_uint(As[mr * SSTR + kb + t + 4]);
                a[mt][3] = __float_as_uint(As[(mr + 8) * SSTR + kb + t + 4]);
            }
            uint32_t b[4][2];
#pragma unroll
            for (int nt = 0; nt < 4; nt++) {
                int nr = wc * 32 + nt * 8 + g;
                b[nt][0] = f2tf(Bs[nr * SSTR + kb + t]);
                b[nt][1] = f2tf(Bs[nr * SSTR + kb + t + 4]);
            }
#pragma unroll
            for (int mt = 0; mt < 4; mt++)
#pragma unroll
                for (int nt = 0; nt < 4; nt++)
                    mma8(c[mt][nt], a[mt], b[nt]);
        }
    }

    // ---- epilogue: (c + bias) * w, atomicAdd scatter into out ----
#pragma unroll
    for (int mt = 0; mt < 4; mt++) {
        int mrow = wr * 64 + mt * 16 + g;
#pragma unroll
        for (int p = 0; p < 2; p++) {
            int slot = m0 + mrow + p * 8;
            bool live = slot < cnt;
            if (!live) continue;
            float w   = g_wts[ebase + slot];
            int   tok = g_tok[ebase + slot];
            float* orow = out + (size_t)tok * DDIM;
#pragma unroll
            for (int nt = 0; nt < 4; nt++) {
                int col = n0 + wc * 32 + nt * 8 + 2 * t;
                float2 db = *(const float2*)(dwb + (size_t)e * DDIM + col);
                float y0 = (c[mt][nt][2 * p + 0] + db.x) * w;
                float y1 = (c[mt][nt][2 * p + 1] + db.y) * w;
                atomicAdd(orow + col, y0);
                atomicAdd(orow + col + 1, y1);
            }
        }
    }
}

// ============================================================
extern "C" void kernel_launch(void* const* d_in, const int* in_sizes, int n_in,
                              void* d_out, int out_size) {
    const float* x      = (const float*)d_in[0];
    const float* gate_w = (const float*)d_in[1];
    const float* gate_b = (const float*)d_in[2];
    const float* up_w   = (const float*)d_in[3];
    const float* up_b   = (const float*)d_in[4];
    const float* gp_w   = (const float*)d_in[5];
    const float* gp_b   = (const float*)d_in[6];
    const float* down_w = (const float*)d_in[7];
    const float* down_b = (const float*)d_in[8];
    float* out = (float*)d_out;
    (void)in_sizes; (void)n_in;

    static int smem_set = 0;
    if (!smem_set) {
        cudaFuncSetAttribute(gemm1_kernel, cudaFuncAttributeMaxDynamicSharedMemorySize,
                             STAGES * 3 * TILE_B);
        cudaFuncSetAttribute(gemm2_kernel, cudaFuncAttributeMaxDynamicSharedMemorySize,
                             STAGES * 2 * TILE_B);
        smem_set = 1;
    }

    init_kernel<<<(out_size + 255) / 256, 256>>>(out, out_size);
    router_kernel<<<NTOK / 8, 256>>>(x, gate_w, gate_b);
    gather_kernel<<<NTOK, 256>>>(x);

    dim3 g1(26, NTOK / BM, NEXP);      // n fastest: A-slab reuse in L2
    gemm1_kernel<<<g1, 256, STAGES * 3 * TILE_B>>>(gp_w, gp_b, up_w, up_b);

    dim3 g2(DDIM / BN, NTOK / BM, NEXP);
    gemm2_kernel<<<g2, 256, STAGES * 2 * TILE_B>>>(down_w, down_b, out);
}

// round 6
// speedup vs baseline: 8.0349x; 1.7681x over previous
#include <cuda_runtime.h>
#include <cuda_fp16.h>
#include <math.h>
#include <stdint.h>

#define NTOK 8192
#define DDIM 1024
#define NEXP 8
#define FDIM 3264
#define NROW (NEXP * NTOK)
#define EFD  (NEXP * FDIM * DDIM)     // 26,738,688 elems per weight tensor

#define BM 128
#define BN 128
#define BK 64                          // halves per k-strip
#define SSTR 72                        // smem row stride in halves (conflict-free)
#define TILE_B (128 * SSTR * 2)        // 18432 bytes per 128-row tile
#define ST1 3                          // gemm1 stages
#define ST2 4                          // gemm2 stages

// ---------------- device scratch ----------------
__device__ int    g_counts[NEXP];
__device__ int    g_pos[NTOK * 2];
__device__ int    g_tok[NROW];
__device__ float  g_wts[NROW];
__device__ __half g_Xe[(size_t)NROW * DDIM];
__device__ __half g_H [(size_t)NROW * FDIM];
__device__ __half g_W16[(size_t)3 * EFD];   // [gp | up | down] in fp16

// ---------------- helpers ----------------
__device__ __forceinline__ uint32_t smem_u32(const void* p) {
    uint32_t a;
    asm("{ .reg .u64 t; cvta.to.shared.u64 t, %1; cvt.u32.u64 %0, t; }" : "=r"(a) : "l"(p));
    return a;
}
__device__ __forceinline__ void cp16(uint32_t dst, const void* src, bool valid) {
    uint32_t sz = valid ? 16u : 0u;
    asm volatile("cp.async.cg.shared.global [%0], [%1], 16, %2;"
                 :: "r"(dst), "l"(src), "r"(sz));
}
__device__ __forceinline__ void cp_commit() {
    asm volatile("cp.async.commit_group;" ::: "memory");
}
__device__ __forceinline__ void cp_wait1() {
    asm volatile("cp.async.wait_group 1;" ::: "memory");
}
__device__ __forceinline__ void cp_wait2() {
    asm volatile("cp.async.wait_group 2;" ::: "memory");
}
__device__ __forceinline__ void mma16(float* c, const uint32_t* a, const uint32_t* b) {
    asm("mma.sync.aligned.m16n8k16.row.col.f32.f16.f16.f32 "
        "{%0,%1,%2,%3}, {%4,%5,%6,%7}, {%8,%9}, {%0,%1,%2,%3};"
        : "+f"(c[0]), "+f"(c[1]), "+f"(c[2]), "+f"(c[3])
        : "r"(a[0]), "r"(a[1]), "r"(a[2]), "r"(a[3]), "r"(b[0]), "r"(b[1]));
}
__device__ __forceinline__ uint32_t ldw(const __half* base, int halfoff) {
    return *(const uint32_t*)(base + halfoff);
}

// ============================================================
// init / conv / router / gather
// ============================================================
__global__ void init_kernel(float* __restrict__ out, int n) {
    int i = blockIdx.x * blockDim.x + threadIdx.x;
    if (i < NEXP) g_counts[i] = 0;
    if (i < n) out[i] = 0.f;
}

__global__ __launch_bounds__(256) void conv_kernel(const float4* __restrict__ src,
                                                   uint2* __restrict__ dst, int n4) {
    int stride = gridDim.x * blockDim.x;
    for (int i = blockIdx.x * blockDim.x + threadIdx.x; i < n4; i += stride) {
        float4 v = src[i];
        __half2 h0 = __floats2half2_rn(v.x, v.y);
        __half2 h1 = __floats2half2_rn(v.z, v.w);
        uint2 o;
        o.x = *(const uint32_t*)&h0;
        o.y = *(const uint32_t*)&h1;
        dst[i] = o;
    }
}

__global__ void router_kernel(const float* __restrict__ x,
                              const float* __restrict__ gw,
                              const float* __restrict__ gb) {
    int warp = (blockIdx.x * blockDim.x + threadIdx.x) >> 5;
    int lane = threadIdx.x & 31;
    if (warp >= NTOK) return;
    const float* xr = x + (size_t)warp * DDIM;

    float acc[NEXP];
#pragma unroll
    for (int e = 0; e < NEXP; e++) acc[e] = 0.f;
    for (int k = lane; k < DDIM; k += 32) {
        float xv = xr[k];
#pragma unroll
        for (int e = 0; e < NEXP; e++) acc[e] += xv * gw[e * DDIM + k];
    }
#pragma unroll
    for (int e = 0; e < NEXP; e++)
#pragma unroll
        for (int off = 16; off; off >>= 1)
            acc[e] += __shfl_xor_sync(0xffffffffu, acc[e], off);

    if (lane == 0) {
        float mx = -1e30f;
#pragma unroll
        for (int e = 0; e < NEXP; e++) { acc[e] += gb[e]; mx = fmaxf(mx, acc[e]); }
        float p[NEXP];
#pragma unroll
        for (int e = 0; e < NEXP; e++) p[e] = expf(acc[e] - mx);
        int i1 = 0; float v1 = p[0];
#pragma unroll
        for (int e = 1; e < NEXP; e++) if (p[e] > v1) { v1 = p[e]; i1 = e; }
        int i2 = -1; float v2 = -1.f;
#pragma unroll
        for (int e = 0; e < NEXP; e++) if (e != i1 && p[e] > v2) { v2 = p[e]; i2 = e; }
        float inv = 1.f / (v1 + v2);
        int s1 = atomicAdd(&g_counts[i1], 1);
        int s2 = atomicAdd(&g_counts[i2], 1);
        g_wts[i1 * NTOK + s1] = v1 * inv;
        g_wts[i2 * NTOK + s2] = v2 * inv;
        g_tok[i1 * NTOK + s1] = warp;
        g_tok[i2 * NTOK + s2] = warp;
        g_pos[2 * warp]     = i1 * NTOK + s1;
        g_pos[2 * warp + 1] = i2 * NTOK + s2;
    }
}

// gather x rows into per-expert slots as fp16
__global__ __launch_bounds__(256) void gather_kernel(const float* __restrict__ x) {
    int t  = blockIdx.x;
    int p0 = g_pos[2 * t], p1 = g_pos[2 * t + 1];
    float4 v = ((const float4*)(x + (size_t)t * DDIM))[threadIdx.x];
    __half2 h0 = __floats2half2_rn(v.x, v.y);
    __half2 h1 = __floats2half2_rn(v.z, v.w);
    uint2 o;
    o.x = *(const uint32_t*)&h0;
    o.y = *(const uint32_t*)&h1;
    ((uint2*)(g_Xe + (size_t)p0 * DDIM))[threadIdx.x] = o;
    ((uint2*)(g_Xe + (size_t)p1 * DDIM))[threadIdx.x] = o;
}

// ============================================================
// GEMM1: [128 slot] x [128 f], K=1024, G and U together, silu -> g_H (fp16)
// ============================================================
__global__ __launch_bounds__(256, 1) void gemm1_kernel(
    const float* __restrict__ gpb, const float* __restrict__ upb) {

    int e   = blockIdx.z;
    int cnt = g_counts[e];
    int m0  = blockIdx.y * BM;
    if (m0 >= cnt) return;
    int n0  = blockIdx.x * BN;
    int ebase = e * NTOK;

    const __half* wg16 = g_W16;             // gp
    const __half* wu16 = g_W16 + EFD;       // up

    extern __shared__ __align__(16) __half sh[];
    uint32_t sbase = smem_u32(sh);

    int tid = threadIdx.x;
    int wid = tid >> 5, lane = tid & 31;
    int wr = wid >> 2, wc = wid & 3;        // 2 x 4 warp grid
    int g = lane >> 2, t = lane & 3;

    const __half* srcA = g_Xe + (size_t)(ebase + m0) * DDIM;

    float cg[4][4][4], cu[4][4][4];
#pragma unroll
    for (int i = 0; i < 4; i++)
#pragma unroll
        for (int j = 0; j < 4; j++)
#pragma unroll
            for (int r = 0; r < 4; r++) { cg[i][j][r] = 0.f; cu[i][j][r] = 0.f; }

    const int KT = DDIM / BK;               // 16

    auto issue = [&](int kt, int st) {
        int k0 = kt * BK;
        uint32_t sA = sbase + st * (3 * TILE_B);
        uint32_t sG = sA + TILE_B;
        uint32_t sU = sG + TILE_B;
#pragma unroll
        for (int i = 0; i < 4; i++) {
            int c = i * 256 + tid;
            int row = c >> 3, kc = c & 7;
            uint32_t doff = (uint32_t)(row * SSTR + kc * 8) * 2;
            cp16(sA + doff, srcA + (size_t)row * DDIM + k0 + kc * 8, true);
            int nrow = n0 + row;
            bool ok = nrow < FDIM;
            int nr = ok ? nrow : (FDIM - 1);
            size_t woff = ((size_t)e * FDIM + nr) * DDIM + k0 + kc * 8;
            cp16(sG + doff, wg16 + woff, ok);
            cp16(sU + doff, wu16 + woff, ok);
        }
        cp_commit();
    };

#pragma unroll
    for (int s = 0; s < ST1 - 1; s++) issue(s, s);

    for (int kt = 0; kt < KT; kt++) {
        cp_wait1();
        __syncthreads();
        if (kt + ST1 - 1 < KT) issue(kt + ST1 - 1, (kt + ST1 - 1) % ST1);
        else cp_commit();

        int st = kt % ST1;
        const __half* As = sh + (size_t)st * (3 * TILE_B / 2);
        const __half* Gs = As + TILE_B / 2;
        const __half* Us = Gs + TILE_B / 2;

#pragma unroll
        for (int kk = 0; kk < 4; kk++) {
            int kb = kk * 16;
            uint32_t a[4][4];
#pragma unroll
            for (int mt = 0; mt < 4; mt++) {
                int mr = wr * 64 + mt * 16 + g;
                a[mt][0] = ldw(As, mr * SSTR + kb + 2 * t);
                a[mt][1] = ldw(As, (mr + 8) * SSTR + kb + 2 * t);
                a[mt][2] = ldw(As, mr * SSTR + kb + 2 * t + 8);
                a[mt][3] = ldw(As, (mr + 8) * SSTR + kb + 2 * t + 8);
            }
            uint32_t bg[4][2], bu[4][2];
#pragma unroll
            for (int nt = 0; nt < 4; nt++) {
                int nr = wc * 32 + nt * 8 + g;
                bg[nt][0] = ldw(Gs, nr * SSTR + kb + 2 * t);
                bg[nt][1] = ldw(Gs, nr * SSTR + kb + 2 * t + 8);
                bu[nt][0] = ldw(Us, nr * SSTR + kb + 2 * t);
                bu[nt][1] = ldw(Us, nr * SSTR + kb + 2 * t + 8);
            }
#pragma unroll
            for (int mt = 0; mt < 4; mt++)
#pragma unroll
                for (int nt = 0; nt < 4; nt++) {
                    mma16(cg[mt][nt], a[mt], bg[nt]);
                    mma16(cu[mt][nt], a[mt], bu[nt]);
                }
        }
    }

    // ---- epilogue: silu(g*u) -> g_H (fp16) ----
#pragma unroll
    for (int mt = 0; mt < 4; mt++) {
        int mrow = wr * 64 + mt * 16 + g;
#pragma unroll
        for (int p = 0; p < 2; p++) {
            int slot = m0 + mrow + p * 8;
            bool live = slot < cnt;
            size_t hbase = ((size_t)ebase + slot) * FDIM;
#pragma unroll
            for (int nt = 0; nt < 4; nt++) {
                int col = n0 + wc * 32 + nt * 8 + 2 * t;
                if (live && col < FDIM) {
                    float2 gb = *(const float2*)(gpb + (size_t)e * FDIM + col);
                    float2 ub = *(const float2*)(upb + (size_t)e * FDIM + col);
                    float g0 = cg[mt][nt][2 * p + 0] + gb.x;
                    float g1 = cg[mt][nt][2 * p + 1] + gb.y;
                    float u0 = cu[mt][nt][2 * p + 0] + ub.x;
                    float u1 = cu[mt][nt][2 * p + 1] + ub.y;
                    float z0 = g0 * u0, z1 = g1 * u1;
                    float h0 = z0 / (1.f + expf(-z0));
                    float h1 = z1 / (1.f + expf(-z1));
                    *(__half2*)(g_H + hbase + col) = __floats2half2_rn(h0, h1);
                }
            }
        }
    }
}

// ============================================================
// GEMM2: [128 slot] x [128 d], K=3264 over g_H (fp16), weighted
// scatter-add into out
// ============================================================
__global__ __launch_bounds__(256, 1) void gemm2_kernel(
    const float* __restrict__ dwb, float* __restrict__ out) {

    int e   = blockIdx.z;
    int cnt = g_counts[e];
    int m0  = blockIdx.y * BM;
    if (m0 >= cnt) return;
    int n0  = blockIdx.x * BN;
    int ebase = e * NTOK;

    const __half* wd16 = g_W16 + 2 * (size_t)EFD;   // down

    extern __shared__ __align__(16) __half sh[];
    uint32_t sbase = smem_u32(sh);

    int tid = threadIdx.x;
    int wid = tid >> 5, lane = tid & 31;
    int wr = wid >> 2, wc = wid & 3;
    int g = lane >> 2, t = lane & 3;

    const __half* srcA = g_H + (size_t)(ebase + m0) * FDIM;

    float c[4][4][4];
#pragma unroll
    for (int i = 0; i < 4; i++)
#pragma unroll
        for (int j = 0; j < 4; j++)
#pragma unroll
            for (int r = 0; r < 4; r++) c[i][j][r] = 0.f;

    const int KT = FDIM / BK;               // 51

    auto issue = [&](int kt, int st) {
        int k0 = kt * BK;
        uint32_t sA = sbase + st * (2 * TILE_B);
        uint32_t sB = sA + TILE_B;
#pragma unroll
        for (int i = 0; i < 4; i++) {
            int cc = i * 256 + tid;
            int row = cc >> 3, kc = cc & 7;
            uint32_t doff = (uint32_t)(row * SSTR + kc * 8) * 2;
            cp16(sA + doff, srcA + (size_t)row * FDIM + k0 + kc * 8, true);
            cp16(sB + doff, wd16 + ((size_t)e * DDIM + n0 + row) * FDIM + k0 + kc * 8, true);
        }
        cp_commit();
    };

#pragma unroll
    for (int s = 0; s < ST2 - 1; s++) issue(s, s);

    for (int kt = 0; kt < KT; kt++) {
        cp_wait2();
        __syncthreads();
        if (kt + ST2 - 1 < KT) issue(kt + ST2 - 1, (kt + ST2 - 1) % ST2);
        else cp_commit();

        int st = kt % ST2;
        const __half* As = sh + (size_t)st * TILE_B;      // 2*TILE_B bytes = TILE_B halves
        const __half* Bs = As + TILE_B / 2;

#pragma unroll
        for (int kk = 0; kk < 4; kk++) {
            int kb = kk * 16;
            uint32_t a[4][4];
#pragma unroll
            for (int mt = 0; mt < 4; mt++) {
                int mr = wr * 64 + mt * 16 + g;
                a[mt][0] = ldw(As, mr * SSTR + kb + 2 * t);
                a[mt][1] = ldw(As, (mr + 8) * SSTR + kb + 2 * t);
                a[mt][2] = ldw(As, mr * SSTR + kb + 2 * t + 8);
                a[mt][3] = ldw(As, (mr + 8) * SSTR + kb + 2 * t + 8);
            }
            uint32_t b[4][2];
#pragma unroll
            for (int nt = 0; nt < 4; nt++) {
                int nr = wc * 32 + nt * 8 + g;
                b[nt][0] = ldw(Bs, nr * SSTR + kb + 2 * t);
                b[nt][1] = ldw(Bs, nr * SSTR + kb + 2 * t + 8);
            }
#pragma unroll
            for (int mt = 0; mt < 4; mt++)
#pragma unroll
                for (int nt = 0; nt < 4; nt++)
                    mma16(c[mt][nt], a[mt], b[nt]);
        }
    }

    // ---- epilogue: (c + bias) * w, atomicAdd scatter into out ----
#pragma unroll
    for (int mt = 0; mt < 4; mt++) {
        int mrow = wr * 64 + mt * 16 + g;
#pragma unroll
        for (int p = 0; p < 2; p++) {
            int slot = m0 + mrow + p * 8;
            if (slot >= cnt) continue;
            float w   = g_wts[ebase + slot];
            int   tok = g_tok[ebase + slot];
            float* orow = out + (size_t)tok * DDIM;
#pragma unroll
            for (int nt = 0; nt < 4; nt++) {
                int col = n0 + wc * 32 + nt * 8 + 2 * t;
                float2 db = *(const float2*)(dwb + (size_t)e * DDIM + col);
                float y0 = (c[mt][nt][2 * p + 0] + db.x) * w;
                float y1 = (c[mt][nt][2 * p + 1] + db.y) * w;
                atomicAdd(orow + col, y0);
                atomicAdd(orow + col + 1, y1);
            }
        }
    }
}

// ============================================================
extern "C" void kernel_launch(void* const* d_in, const int* in_sizes, int n_in,
                              void* d_out, int out_size) {
    const float* x      = (const float*)d_in[0];
    const float* gate_w = (const float*)d_in[1];
    const float* gate_b = (const float*)d_in[2];
    const float* up_w   = (const float*)d_in[3];
    const float* up_b   = (const float*)d_in[4];
    const float* gp_w   = (const float*)d_in[5];
    const float* gp_b   = (const float*)d_in[6];
    const float* down_w = (const float*)d_in[7];
    const float* down_b = (const float*)d_in[8];
    float* out = (float*)d_out;
    (void)in_sizes; (void)n_in;

    cudaFuncSetAttribute(gemm1_kernel, cudaFuncAttributeMaxDynamicSharedMemorySize,
                         ST1 * 3 * TILE_B);
    cudaFuncSetAttribute(gemm2_kernel, cudaFuncAttributeMaxDynamicSharedMemorySize,
                         ST2 * 2 * TILE_B);

    void* w16p = nullptr;
    cudaGetSymbolAddress(&w16p, g_W16);
    __half* w16 = (__half*)w16p;

    init_kernel<<<(out_size + 255) / 256, 256>>>(out, out_size);
    router_kernel<<<NTOK / 8, 256>>>(x, gate_w, gate_b);
    gather_kernel<<<NTOK, 256>>>(x);

    conv_kernel<<<2048, 256>>>((const float4*)gp_w,   (uint2*)(w16),           EFD / 4);
    conv_kernel<<<2048, 256>>>((const float4*)up_w,   (uint2*)(w16 + EFD),     EFD / 4);
    conv_kernel<<<2048, 256>>>((const float4*)down_w, (uint2*)(w16 + 2 * (size_t)EFD), EFD / 4);

    dim3 g1(26, NTOK / BM, NEXP);
    gemm1_kernel<<<g1, 256, ST1 * 3 * TILE_B>>>(gp_b, up_b);

    dim3 g2(DDIM / BN, NTOK / BM, NEXP);
    gemm2_kernel<<<g2, 256, ST2 * 2 * TILE_B>>>(down_b, out);
}